// round 1
// baseline (speedup 1.0000x reference)
#include <cuda_runtime.h>
#include <cuda_bf16.h>

#define N_NODES 100000
#define N_GRAPHS 64
#define FEAT 64

// ---------------- scratch (device globals; no allocations) ----------------
__device__ float g_S[N_NODES * FEAT];     // scatter-sum accumulator
__device__ float g_h[N_NODES * FEAT];     // layer output (reused in-place)
__device__ int   g_cnt[N_NODES];          // in-degree
__device__ float g_pooled[N_GRAPHS * FEAT];
__device__ int   g_ei64;                  // edge_index is int64?
__device__ int   g_b64;                   // batch is int64?

// ---------------- dtype detection (int32 vs int64 indices) ----------------
__global__ void detect_kernel(const void* ei, const void* batch, int nE, int nN) {
    if (threadIdx.x == 0 && blockIdx.x == 0) {
        // edge_index: values must be in [0, nN). If really int32, a 64-bit read
        // combines two random int32s -> almost surely out of range.
        int e64 = 1;
        const long long* p = (const long long*)ei;
        for (int i = 0; i < 64 && i < nE; i++) {
            long long v = p[i];
            if (v < 0 || v >= (long long)nN) { e64 = 0; break; }
        }
        g_ei64 = e64;
        // batch: sorted 0..63; probe near the END of the int32-sized footprint
        // (safe either way: index nN/2-1 in 64-bit units is within nN*4 bytes).
        int b64 = 1;
        const long long* q = (const long long*)batch;
        for (int i = 0; i < 8; i++) {
            int idx = nN / 2 - 1 - i;
            if (idx < 0) break;
            long long v = q[idx];
            if (v < 0 || v >= 64) { b64 = 0; break; }
        }
        g_b64 = b64;
    }
}

// ---------------- zero scratch ----------------
__global__ void zero_scratch(int nN, int withCnt) {
    int i = blockIdx.x * blockDim.x + threadIdx.x;
    int total4 = nN * 16;   // nN*64 floats as float4
    if (i < total4) reinterpret_cast<float4*>(g_S)[i] = make_float4(0.f, 0.f, 0.f, 0.f);
    if (withCnt && i < nN) g_cnt[i] = 0;
}

// ---------------- edge scatter: S[dst] += feat[src], cnt[dst]++ ------------
// 16 threads per edge, one float4 chunk each. Loads coalesced (256B/edge),
// vector reductions to L2 (rows are L2-resident: 25.6MB each side).
__global__ void scatter_kernel(const float* __restrict__ x, const void* __restrict__ ei_v,
                               int nE, int doCount, int fromH) {
    int idx = blockIdx.x * blockDim.x + threadIdx.x;
    if (idx >= nE * 16) return;
    int e = idx >> 4;
    int c = idx & 15;
    int is64 = g_ei64;
    int src, dst;
    if (is64) {
        const long long* ei = (const long long*)ei_v;
        src = (int)ei[e];
        dst = (int)ei[(long long)nE + e];
    } else {
        const int* ei = (const int*)ei_v;
        src = ei[e];
        dst = ei[nE + e];
    }
    const float* base = fromH ? g_h : x;
    float4 v = *reinterpret_cast<const float4*>(base + (long long)src * FEAT + c * 4);
    float* p = g_S + (long long)dst * FEAT + c * 4;
    asm volatile("red.global.add.v4.f32 [%0], {%1, %2, %3, %4};"
                 :: "l"(p), "f"(v.x), "f"(v.y), "f"(v.z), "f"(v.w) : "memory");
    if (doCount && c == 0) atomicAdd(&g_cnt[dst], 1);
}

// ---------------- fused RGCN layer GEMM --------------------------------
// out[i,:] = relu( (S[i,:]/max(cnt,1)) @ Wrel  +  X[i,:] @ Wroot  +  b )
// Tile: 64 rows x 64 cols per block, 256 threads, each thread 4x4 outputs.
// K=128 (concat of scaled-S and X against concat(Wrel;Wroot)).
__global__ void rgcn_gemm(const float* __restrict__ Xin,
                          const float* __restrict__ Wrel,
                          const float* __restrict__ Wroot,
                          const float* __restrict__ bias,
                          int nRows, int xIsH) {
    const float* X = xIsH ? (const float*)g_h : Xin;
    __shared__ float4 sW[128][16];   // [k][j4]  (k<64: Wrel, k>=64: Wroot)
    __shared__ float4 sIn[64][33];   // [row][k4], padded vs bank conflicts
    __shared__ float  sB[64];

    int tid = threadIdx.x;
    int rowBase = blockIdx.x * 64;

    #pragma unroll
    for (int i = tid; i < 2048; i += 256) {
        int k = i >> 4, j = i & 15;
        sW[k][j] = (k < 64) ? reinterpret_cast<const float4*>(Wrel)[k * 16 + j]
                            : reinterpret_cast<const float4*>(Wroot)[(k - 64) * 16 + j];
    }
    if (tid < 64) sB[tid] = bias[tid];

    #pragma unroll
    for (int i = tid; i < 2048; i += 256) {
        int r = i >> 5, q = i & 31;
        int row = rowBase + r;
        float4 v = make_float4(0.f, 0.f, 0.f, 0.f);
        if (row < nRows) {
            if (q < 16) {
                v = reinterpret_cast<const float4*>(g_S)[row * 16 + q];
                float inv = 1.0f / fmaxf((float)g_cnt[row], 1.0f);
                v.x *= inv; v.y *= inv; v.z *= inv; v.w *= inv;
            } else {
                v = reinterpret_cast<const float4*>(X)[row * 16 + (q - 16)];
            }
        }
        sIn[r][q] = v;
    }
    __syncthreads();

    int tx = tid & 15;   // 4-col group
    int ty = tid >> 4;   // row within 16
    float acc[4][4];
    #pragma unroll
    for (int i = 0; i < 4; i++)
        #pragma unroll
        for (int j = 0; j < 4; j++) acc[i][j] = 0.f;

    #pragma unroll 8
    for (int k4 = 0; k4 < 32; ++k4) {
        float4 a0 = sIn[ty      ][k4];
        float4 a1 = sIn[ty + 16][k4];
        float4 a2 = sIn[ty + 32][k4];
        float4 a3 = sIn[ty + 48][k4];
        float4 w0 = sW[4 * k4 + 0][tx];
        float4 w1 = sW[4 * k4 + 1][tx];
        float4 w2 = sW[4 * k4 + 2][tx];
        float4 w3 = sW[4 * k4 + 3][tx];
        float4 a[4] = {a0, a1, a2, a3};
        #pragma unroll
        for (int i = 0; i < 4; i++) {
            acc[i][0] += a[i].x * w0.x + a[i].y * w1.x + a[i].z * w2.x + a[i].w * w3.x;
            acc[i][1] += a[i].x * w0.y + a[i].y * w1.y + a[i].z * w2.y + a[i].w * w3.y;
            acc[i][2] += a[i].x * w0.z + a[i].y * w1.z + a[i].z * w2.z + a[i].w * w3.z;
            acc[i][3] += a[i].x * w0.w + a[i].y * w1.w + a[i].z * w2.w + a[i].w * w3.w;
        }
    }

    #pragma unroll
    for (int i = 0; i < 4; i++) {
        int row = rowBase + ty + 16 * i;
        if (row < nRows) {
            float4 o;
            o.x = fmaxf(acc[i][0] + sB[tx * 4 + 0], 0.f);
            o.y = fmaxf(acc[i][1] + sB[tx * 4 + 1], 0.f);
            o.z = fmaxf(acc[i][2] + sB[tx * 4 + 2], 0.f);
            o.w = fmaxf(acc[i][3] + sB[tx * 4 + 3], 0.f);
            reinterpret_cast<float4*>(g_h)[row * 16 + tx] = o;
        }
    }
}

// ---------------- global mean pool: one block per graph (batch sorted) ----
__device__ __forceinline__ long long batch_at(const void* b, int i, int is64) {
    return is64 ? ((const long long*)b)[i] : (long long)((const int*)b)[i];
}

__global__ void pool_kernel(const void* __restrict__ batch, int nRows) {
    int g = blockIdx.x;
    int is64 = g_b64;
    // lower_bound(batch, g) and lower_bound(batch, g+1)
    int lo = 0, hi = nRows;
    while (lo < hi) { int m = (lo + hi) >> 1; if (batch_at(batch, m, is64) < g) lo = m + 1; else hi = m; }
    int start = lo;
    lo = 0; hi = nRows;
    while (lo < hi) { int m = (lo + hi) >> 1; if (batch_at(batch, m, is64) < g + 1) lo = m + 1; else hi = m; }
    int end = lo;

    int feat = threadIdx.x & 63;
    int rl   = threadIdx.x >> 6;    // 0..3
    float s = 0.f;
    for (int r = start + rl; r < end; r += 4)
        s += g_h[(long long)r * FEAT + feat];

    __shared__ float sm[4][64];
    sm[rl][feat] = s;
    __syncthreads();
    if (rl == 0) {
        float tot = sm[0][feat] + sm[1][feat] + sm[2][feat] + sm[3][feat];
        g_pooled[g * FEAT + feat] = tot / fmaxf((float)(end - start), 1.0f);
    }
}

// ---------------- heads: hidden, cell, log_softmax(logits) -----------------
// out layout: logits[64*32] | hidden[64*64] | cell[64*64]
__global__ void head_kernel(const float* __restrict__ Wh, const float* __restrict__ bh,
                            const float* __restrict__ Wc, const float* __restrict__ bc,
                            const float* __restrict__ Wo, const float* __restrict__ bo,
                            float* __restrict__ out) {
    __shared__ float sp[64 * 64];
    __shared__ float sh[64 * 64];
    int tid = threadIdx.x;

    for (int i = tid; i < 4096; i += 256) sp[i] = g_pooled[i];
    __syncthreads();

    for (int i = tid; i < 4096; i += 256) {
        int g = i >> 6, j = i & 63;
        float ah = bh[j], ac = bc[j];
        #pragma unroll 8
        for (int k = 0; k < 64; k++) {
            float p = sp[g * 64 + k];
            ah += p * Wh[k * 64 + j];
            ac += p * Wc[k * 64 + j];
        }
        sh[i] = ah;
        out[2048 + i] = ah;          // hidden
        out[2048 + 4096 + i] = ac;   // cell
    }
    __syncthreads();

    int warp = tid >> 5, lane = tid & 31;   // 8 warps, lane = vocab col
    for (int g = warp; g < 64; g += 8) {
        float z = bo[lane];
        #pragma unroll 8
        for (int k = 0; k < 64; k++)
            z += sh[g * 64 + k] * Wo[k * 32 + lane];
        float m = z;
        #pragma unroll
        for (int off = 16; off > 0; off >>= 1)
            m = fmaxf(m, __shfl_xor_sync(0xffffffffu, m, off));
        float s = expf(z - m);
        #pragma unroll
        for (int off = 16; off > 0; off >>= 1)
            s += __shfl_xor_sync(0xffffffffu, s, off);
        out[g * 32 + lane] = z - m - logf(s);
    }
}

// ---------------- launch ----------------
extern "C" void kernel_launch(void* const* d_in, const int* in_sizes, int n_in,
                              void* d_out, int out_size) {
    const float* x     = (const float*)d_in[0];
    const void*  ei    = d_in[1];
    const void*  batch = d_in[2];
    const float* W1    = (const float*)d_in[3];
    const float* root1 = (const float*)d_in[4];
    const float* b1    = (const float*)d_in[5];
    const float* W2    = (const float*)d_in[6];
    const float* root2 = (const float*)d_in[7];
    const float* b2    = (const float*)d_in[8];
    const float* Wh    = (const float*)d_in[9];
    const float* bh    = (const float*)d_in[10];
    const float* Wc    = (const float*)d_in[11];
    const float* bc    = (const float*)d_in[12];
    const float* Wo    = (const float*)d_in[13];
    const float* bo    = (const float*)d_in[14];

    int nN = in_sizes[0] / FEAT;   // 100000
    int nE = in_sizes[1] / 2;      // 1600000

    int zBlocks  = (nN * 16 + 255) / 256;
    int scBlocks = (nE * 16 + 255) / 256;
    int gBlocks  = (nN + 63) / 64;

    detect_kernel<<<1, 32>>>(ei, batch, nE, nN);

    // layer 1
    zero_scratch<<<zBlocks, 256>>>(nN, 1);
    scatter_kernel<<<scBlocks, 256>>>(x, ei, nE, 1, 0);
    rgcn_gemm<<<gBlocks, 256>>>(x, W1, root1, b1, nN, 0);

    // layer 2 (reads g_h, writes g_h in-place; safe: per-block rows only)
    zero_scratch<<<zBlocks, 256>>>(nN, 0);
    scatter_kernel<<<scBlocks, 256>>>(x, ei, nE, 0, 1);
    rgcn_gemm<<<gBlocks, 256>>>(x, W2, root2, b2, nN, 1);

    // pool + heads
    pool_kernel<<<N_GRAPHS, 256>>>(batch, nN);
    head_kernel<<<1, 256>>>(Wh, bh, Wc, bc, Wo, bo, (float*)d_out);
}

// round 2
// speedup vs baseline: 1.3159x; 1.3159x over previous
#include <cuda_runtime.h>
#include <cuda_bf16.h>

#define MAX_N 100000
#define N_GRAPHS 64
#define FEAT 64
#define MAX_E 1600000

// ---------------- scratch (device globals; no allocations) ----------------
__device__ float g_S[MAX_N * FEAT];       // aggregated (mean) neighbor features
__device__ float g_h[MAX_N * FEAT];       // layer output (reused in-place)
__device__ int   g_deg[MAX_N];            // in-degree histogram
__device__ int   g_rowstart[MAX_N + 1];   // CSR row starts (exclusive scan of deg)
__device__ int   g_cursor[MAX_N];         // placement cursors
__device__ int   g_srcs[MAX_E];           // CSR: src node per edge, bucketed by dst
__device__ int   g_bsum[128];             // scan block sums
__device__ int   g_boff[128];             // scanned block offsets
__device__ float g_pooled[N_GRAPHS * FEAT];
__device__ int   g_ei64;                  // edge_index is int64?
__device__ int   g_b64;                   // batch is int64?

// ---------------- dtype detection (int32 vs int64 indices) ----------------
__global__ void detect_kernel(const void* ei, const void* batch, int nE, int nN) {
    if (threadIdx.x == 0 && blockIdx.x == 0) {
        int e64 = 1;
        const long long* p = (const long long*)ei;
        for (int i = 0; i < 64 && i < nE; i++) {
            long long v = p[i];
            if (v < 0 || v >= (long long)nN) { e64 = 0; break; }
        }
        g_ei64 = e64;
        int b64 = 1;
        const long long* q = (const long long*)batch;
        for (int i = 0; i < 8; i++) {
            int idx = nN / 2 - 1 - i;
            if (idx < 0) break;
            long long v = q[idx];
            if (v < 0 || v >= 64) { b64 = 0; break; }
        }
        g_b64 = b64;
    }
}

// ---------------- CSR build: histogram ----------------
__global__ void zero_deg_kernel(int nN) {
    int i = blockIdx.x * blockDim.x + threadIdx.x;
    if (i < nN) g_deg[i] = 0;
}

__global__ void hist_kernel(const void* __restrict__ ei_v, int nE) {
    int e = blockIdx.x * blockDim.x + threadIdx.x;
    if (e >= nE) return;
    int dst;
    if (g_ei64) dst = (int)((const long long*)ei_v)[(long long)nE + e];
    else        dst = ((const int*)ei_v)[nE + e];
    atomicAdd(&g_deg[dst], 1);
}

// ---------------- CSR build: 3-phase exclusive scan over deg ----------------
// Phase 1: per-block (1024 items) exclusive scan; block totals -> g_bsum
__global__ void scan_block_kernel(int nN) {
    __shared__ int wsum[8];
    __shared__ int woff[8];
    int blk = blockIdx.x, t = threadIdx.x;
    int base = blk * 1024 + t * 4;
    int v0 = (base + 0 < nN) ? g_deg[base + 0] : 0;
    int v1 = (base + 1 < nN) ? g_deg[base + 1] : 0;
    int v2 = (base + 2 < nN) ? g_deg[base + 2] : 0;
    int v3 = (base + 3 < nN) ? g_deg[base + 3] : 0;
    int i0 = v0, i1 = i0 + v1, i2 = i1 + v2, i3 = i2 + v3;
    int tot = i3;
    int lane = t & 31, w = t >> 5;
    int sc = tot;
    #pragma unroll
    for (int off = 1; off < 32; off <<= 1) {
        int n = __shfl_up_sync(0xffffffffu, sc, off);
        if (lane >= off) sc += n;
    }
    if (lane == 31) wsum[w] = sc;
    __syncthreads();
    if (t < 8) {
        int v = wsum[t];
        int s = v;
        #pragma unroll
        for (int off = 1; off < 8; off <<= 1) {
            int n = __shfl_up_sync(0xffu, s, off);
            if (t >= off) s += n;
        }
        woff[t] = s - v;
        if (t == 7) g_bsum[blk] = s;
    }
    __syncthreads();
    int excl = woff[w] + (sc - tot);
    if (base + 0 < nN) g_rowstart[base + 0] = excl;
    if (base + 1 < nN) g_rowstart[base + 1] = excl + i0;
    if (base + 2 < nN) g_rowstart[base + 2] = excl + i1;
    if (base + 3 < nN) g_rowstart[base + 3] = excl + i2;
}

// Phase 2: single block scans <=128 block sums -> g_boff (exclusive)
__global__ void scan_tops_kernel(int nBlocks) {
    __shared__ int wsum[4];
    __shared__ int woff[4];
    int t = threadIdx.x;  // 128 threads
    int v = (t < nBlocks) ? g_bsum[t] : 0;
    int lane = t & 31, w = t >> 5;
    int s = v;
    #pragma unroll
    for (int off = 1; off < 32; off <<= 1) {
        int n = __shfl_up_sync(0xffffffffu, s, off);
        if (lane >= off) s += n;
    }
    if (lane == 31) wsum[w] = s;
    __syncthreads();
    if (t < 4) {
        int vv = wsum[t];
        int ss = vv;
        #pragma unroll
        for (int off = 1; off < 4; off <<= 1) {
            int n = __shfl_up_sync(0xfu, ss, off);
            if (t >= off) ss += n;
        }
        woff[t] = ss - vv;
    }
    __syncthreads();
    if (t < nBlocks) g_boff[t] = (s - v) + woff[w];
}

// Phase 3: add block offsets; init cursors; set sentinel
__global__ void scan_add_kernel(int nN, int nE) {
    int i = blockIdx.x * blockDim.x + threadIdx.x;
    if (i < nN) {
        int s = g_rowstart[i] + g_boff[i >> 10];
        g_rowstart[i] = s;
        g_cursor[i] = s;
    }
    if (i == 0) g_rowstart[nN] = nE;
}

// ---------------- CSR build: placement ----------------
__global__ void fill_kernel(const void* __restrict__ ei_v, int nE) {
    int e = blockIdx.x * blockDim.x + threadIdx.x;
    if (e >= nE) return;
    int src, dst;
    if (g_ei64) {
        const long long* ei = (const long long*)ei_v;
        src = (int)ei[e];
        dst = (int)ei[(long long)nE + e];
    } else {
        const int* ei = (const int*)ei_v;
        src = ei[e];
        dst = ei[nE + e];
    }
    int pos = atomicAdd(&g_cursor[dst], 1);
    g_srcs[pos] = src;
}

// ---------------- gather-mean: S[i,:] = mean_{j in N(i)} feat[j,:] ----------
// 16 threads per node, one float4 column chunk each; coalesced 256B row reads.
__global__ void gather_kernel(const float* __restrict__ x, int nN, int fromH) {
    int idx = blockIdx.x * blockDim.x + threadIdx.x;
    int node = idx >> 4;
    int c = idx & 15;
    if (node >= nN) return;
    const float* base = fromH ? (const float*)g_h : x;
    int s = g_rowstart[node];
    int e = g_rowstart[node + 1];
    float4 acc = make_float4(0.f, 0.f, 0.f, 0.f);
    int i = s;
    for (; i + 2 <= e; i += 2) {
        int s0 = __ldg(&g_srcs[i]);
        int s1 = __ldg(&g_srcs[i + 1]);
        float4 v0 = __ldg((const float4*)(base + (size_t)s0 * FEAT) + c);
        float4 v1 = __ldg((const float4*)(base + (size_t)s1 * FEAT) + c);
        acc.x += v0.x + v1.x; acc.y += v0.y + v1.y;
        acc.z += v0.z + v1.z; acc.w += v0.w + v1.w;
    }
    if (i < e) {
        int s0 = __ldg(&g_srcs[i]);
        float4 v0 = __ldg((const float4*)(base + (size_t)s0 * FEAT) + c);
        acc.x += v0.x; acc.y += v0.y; acc.z += v0.z; acc.w += v0.w;
    }
    float inv = 1.0f / fmaxf((float)(e - s), 1.0f);
    float4 o = make_float4(acc.x * inv, acc.y * inv, acc.z * inv, acc.w * inv);
    reinterpret_cast<float4*>(g_S)[node * 16 + c] = o;
}

// ---------------- fused RGCN layer GEMM --------------------------------
// out[i,:] = relu( S[i,:] @ Wrel + X[i,:] @ Wroot + b ), K=128 fused.
__global__ void rgcn_gemm(const float* __restrict__ Xin,
                          const float* __restrict__ Wrel,
                          const float* __restrict__ Wroot,
                          const float* __restrict__ bias,
                          int nRows, int xIsH) {
    const float* X = xIsH ? (const float*)g_h : Xin;
    __shared__ float4 sW[128][16];
    __shared__ float4 sIn[64][33];
    __shared__ float  sB[64];

    int tid = threadIdx.x;
    int rowBase = blockIdx.x * 64;

    #pragma unroll
    for (int i = tid; i < 2048; i += 256) {
        int k = i >> 4, j = i & 15;
        sW[k][j] = (k < 64) ? reinterpret_cast<const float4*>(Wrel)[k * 16 + j]
                            : reinterpret_cast<const float4*>(Wroot)[(k - 64) * 16 + j];
    }
    if (tid < 64) sB[tid] = bias[tid];

    #pragma unroll
    for (int i = tid; i < 2048; i += 256) {
        int r = i >> 5, q = i & 31;
        int row = rowBase + r;
        float4 v = make_float4(0.f, 0.f, 0.f, 0.f);
        if (row < nRows) {
            if (q < 16) v = reinterpret_cast<const float4*>(g_S)[row * 16 + q];
            else        v = reinterpret_cast<const float4*>(X)[row * 16 + (q - 16)];
        }
        sIn[r][q] = v;
    }
    __syncthreads();

    int tx = tid & 15;
    int ty = tid >> 4;
    float acc[4][4];
    #pragma unroll
    for (int i = 0; i < 4; i++)
        #pragma unroll
        for (int j = 0; j < 4; j++) acc[i][j] = 0.f;

    #pragma unroll 8
    for (int k4 = 0; k4 < 32; ++k4) {
        float4 a0 = sIn[ty      ][k4];
        float4 a1 = sIn[ty + 16][k4];
        float4 a2 = sIn[ty + 32][k4];
        float4 a3 = sIn[ty + 48][k4];
        float4 w0 = sW[4 * k4 + 0][tx];
        float4 w1 = sW[4 * k4 + 1][tx];
        float4 w2 = sW[4 * k4 + 2][tx];
        float4 w3 = sW[4 * k4 + 3][tx];
        float4 a[4] = {a0, a1, a2, a3};
        #pragma unroll
        for (int i = 0; i < 4; i++) {
            acc[i][0] += a[i].x * w0.x + a[i].y * w1.x + a[i].z * w2.x + a[i].w * w3.x;
            acc[i][1] += a[i].x * w0.y + a[i].y * w1.y + a[i].z * w2.y + a[i].w * w3.y;
            acc[i][2] += a[i].x * w0.z + a[i].y * w1.z + a[i].z * w2.z + a[i].w * w3.z;
            acc[i][3] += a[i].x * w0.w + a[i].y * w1.w + a[i].z * w2.w + a[i].w * w3.w;
        }
    }

    #pragma unroll
    for (int i = 0; i < 4; i++) {
        int row = rowBase + ty + 16 * i;
        if (row < nRows) {
            float4 o;
            o.x = fmaxf(acc[i][0] + sB[tx * 4 + 0], 0.f);
            o.y = fmaxf(acc[i][1] + sB[tx * 4 + 1], 0.f);
            o.z = fmaxf(acc[i][2] + sB[tx * 4 + 2], 0.f);
            o.w = fmaxf(acc[i][3] + sB[tx * 4 + 3], 0.f);
            reinterpret_cast<float4*>(g_h)[row * 16 + tx] = o;
        }
    }
}

// ---------------- global mean pool: one block per graph (batch sorted) ----
__device__ __forceinline__ long long batch_at(const void* b, int i, int is64) {
    return is64 ? ((const long long*)b)[i] : (long long)((const int*)b)[i];
}

__global__ void pool_kernel(const void* __restrict__ batch, int nRows) {
    int g = blockIdx.x;
    int is64 = g_b64;
    int lo = 0, hi = nRows;
    while (lo < hi) { int m = (lo + hi) >> 1; if (batch_at(batch, m, is64) < g) lo = m + 1; else hi = m; }
    int start = lo;
    lo = 0; hi = nRows;
    while (lo < hi) { int m = (lo + hi) >> 1; if (batch_at(batch, m, is64) < g + 1) lo = m + 1; else hi = m; }
    int end = lo;

    int feat = threadIdx.x & 63;
    int rl   = threadIdx.x >> 6;
    float s = 0.f;
    for (int r = start + rl; r < end; r += 4)
        s += g_h[(long long)r * FEAT + feat];

    __shared__ float sm[4][64];
    sm[rl][feat] = s;
    __syncthreads();
    if (rl == 0) {
        float tot = sm[0][feat] + sm[1][feat] + sm[2][feat] + sm[3][feat];
        g_pooled[g * FEAT + feat] = tot / fmaxf((float)(end - start), 1.0f);
    }
}

// ---------------- heads: hidden, cell, log_softmax(logits) -----------------
__global__ void head_kernel(const float* __restrict__ Wh, const float* __restrict__ bh,
                            const float* __restrict__ Wc, const float* __restrict__ bc,
                            const float* __restrict__ Wo, const float* __restrict__ bo,
                            float* __restrict__ out) {
    __shared__ float sp[64 * 64];
    __shared__ float sh[64 * 64];
    int tid = threadIdx.x;

    for (int i = tid; i < 4096; i += 256) sp[i] = g_pooled[i];
    __syncthreads();

    for (int i = tid; i < 4096; i += 256) {
        int g = i >> 6, j = i & 63;
        float ah = bh[j], ac = bc[j];
        #pragma unroll 8
        for (int k = 0; k < 64; k++) {
            float p = sp[g * 64 + k];
            ah += p * Wh[k * 64 + j];
            ac += p * Wc[k * 64 + j];
        }
        sh[i] = ah;
        out[2048 + i] = ah;
        out[2048 + 4096 + i] = ac;
    }
    __syncthreads();

    int warp = tid >> 5, lane = tid & 31;
    for (int g = warp; g < 64; g += 8) {
        float z = bo[lane];
        #pragma unroll 8
        for (int k = 0; k < 64; k++)
            z += sh[g * 64 + k] * Wo[k * 32 + lane];
        float m = z;
        #pragma unroll
        for (int off = 16; off > 0; off >>= 1)
            m = fmaxf(m, __shfl_xor_sync(0xffffffffu, m, off));
        float s = expf(z - m);
        #pragma unroll
        for (int off = 16; off > 0; off >>= 1)
            s += __shfl_xor_sync(0xffffffffu, s, off);
        out[g * 32 + lane] = z - m - logf(s);
    }
}

// ---------------- launch ----------------
extern "C" void kernel_launch(void* const* d_in, const int* in_sizes, int n_in,
                              void* d_out, int out_size) {
    const float* x     = (const float*)d_in[0];
    const void*  ei    = d_in[1];
    const void*  batch = d_in[2];
    const float* W1    = (const float*)d_in[3];
    const float* root1 = (const float*)d_in[4];
    const float* b1    = (const float*)d_in[5];
    const float* W2    = (const float*)d_in[6];
    const float* root2 = (const float*)d_in[7];
    const float* b2    = (const float*)d_in[8];
    const float* Wh    = (const float*)d_in[9];
    const float* bh    = (const float*)d_in[10];
    const float* Wc    = (const float*)d_in[11];
    const float* bc    = (const float*)d_in[12];
    const float* Wo    = (const float*)d_in[13];
    const float* bo    = (const float*)d_in[14];

    int nN = in_sizes[0] / FEAT;   // 100000
    int nE = in_sizes[1] / 2;      // 1600000

    int eBlocks = (nE + 255) / 256;
    int nBlocks = (nN + 255) / 256;
    int scanBlocks = (nN + 1023) / 1024;      // <=128
    int gatherBlocks = (nN * 16 + 255) / 256;
    int gemmBlocks = (nN + 63) / 64;

    detect_kernel<<<1, 32>>>(ei, batch, nE, nN);

    // ---- CSR build (once per call) ----
    zero_deg_kernel<<<nBlocks, 256>>>(nN);
    hist_kernel<<<eBlocks, 256>>>(ei, nE);
    scan_block_kernel<<<scanBlocks, 256>>>(nN);
    scan_tops_kernel<<<1, 128>>>(scanBlocks);
    scan_add_kernel<<<nBlocks, 256>>>(nN, nE);
    fill_kernel<<<eBlocks, 256>>>(ei, nE);

    // ---- layer 1 ----
    gather_kernel<<<gatherBlocks, 256>>>(x, nN, 0);
    rgcn_gemm<<<gemmBlocks, 256>>>(x, W1, root1, b1, nN, 0);

    // ---- layer 2 ----
    gather_kernel<<<gatherBlocks, 256>>>(x, nN, 1);
    rgcn_gemm<<<gemmBlocks, 256>>>(x, W2, root2, b2, nN, 1);

    // ---- pool + heads ----
    pool_kernel<<<N_GRAPHS, 256>>>(batch, nN);
    head_kernel<<<1, 256>>>(Wh, bh, Wc, bc, Wo, bo, (float*)d_out);
}